// round 1
// baseline (speedup 1.0000x reference)
#include <cuda_runtime.h>

// LSTMBaseline: 2-layer LSTM (B=2048, T=512, H=128, in=2) + ReLU MLP head -> [B,2]
//
// Strategy: batch-parallel persistent CTAs. 128 CTAs x 256 threads, each CTA
// owns 16 batch rows for all 512 timesteps of both layers. Cell state in
// registers; h state ping-pongs in shared memory; weights prepacked into a
// coalesced per-lane float4 layout in __device__ scratch by a prep kernel.

#define T_STEPS 512
#define HID     128
#define MROWS   16
#define NCTA    128
#define NTHR    256

// Prepacked weights (device scratch -- no allocation at runtime)
__device__ float d_WT0[512 * 128];   // layer0 recurrent, packed (256 KB)
__device__ float d_WT1[512 * 256];   // layer1 [w_ih1 | w_hh1] packed (512 KB)
__device__ float d_B0[512];          // b_ih0 + b_hh0
__device__ float d_B1[512];          // b_ih1 + b_hh1

// Packed float4 index: i = ((kb*4 + offi)*64 + u2)*2 + uu
//   holds w[g][kb*4 .. kb*4+3] with g = offi*128 + u2*2 + uu
__global__ void prep_kernel(const float* __restrict__ w_hh0,
                            const float* __restrict__ w_ih1,
                            const float* __restrict__ w_hh1,
                            const float* __restrict__ b_ih0,
                            const float* __restrict__ b_hh0,
                            const float* __restrict__ b_ih1,
                            const float* __restrict__ b_hh1)
{
    int i = blockIdx.x * blockDim.x + threadIdx.x;

    if (i < 16384) {   // WT0: 512*128 floats = 16384 float4
        int uu = i & 1, u2 = (i >> 1) & 63, blk = i >> 7;
        int offi = blk & 3, kb = blk >> 2;          // kb in [0,32)
        int g = offi * 128 + u2 * 2 + uu;
        const float* src = w_hh0 + g * 128 + kb * 4;
        float4 v = make_float4(src[0], src[1], src[2], src[3]);
        reinterpret_cast<float4*>(d_WT0)[i] = v;
    }
    if (i < 32768) {   // WT1: 512*256 floats = 32768 float4, kb in [0,64)
        int uu = i & 1, u2 = (i >> 1) & 63, blk = i >> 7;
        int offi = blk & 3, kb = blk >> 2;
        int g = offi * 128 + u2 * 2 + uu;
        float vv[4];
#pragma unroll
        for (int kk = 0; kk < 4; kk++) {
            int k = kb * 4 + kk;
            vv[kk] = (k < 128) ? w_ih1[g * 128 + k]
                               : w_hh1[g * 128 + (k - 128)];
        }
        reinterpret_cast<float4*>(d_WT1)[i] = make_float4(vv[0], vv[1], vv[2], vv[3]);
    }
    if (i < 512) {
        d_B0[i] = b_ih0[i] + b_hh0[i];
        d_B1[i] = b_ih1[i] + b_hh1[i];
    }
}

__device__ __forceinline__ float sigmoidf_(float x)
{
    return 1.0f / (1.0f + __expf(-x));
}

__device__ __forceinline__ float dot4(float4 h, float4 w, float a)
{
    a = fmaf(h.x, w.x, a);
    a = fmaf(h.y, w.y, a);
    a = fmaf(h.z, w.z, a);
    a = fmaf(h.w, w.w, a);
    return a;
}

// One 128-wide K-chunk (32 kb-iterations) of the recurrent GEMM.
// hsrc: [MROWS][HID] shared tile; Wbase: per-lane adjusted packed weights.
// KB0 selects the K-offset inside the packed weight matrix.
template <int KB0>
__device__ __forceinline__ void gemm128(const float (*hsrc)[HID], int m0,
                                        const float4* __restrict__ Wbase,
                                        float acc[4][8])
{
#pragma unroll 2
    for (int kb = 0; kb < 32; kb++) {
        float4 hv[4];
#pragma unroll
        for (int mi = 0; mi < 4; mi++)
            hv[mi] = *reinterpret_cast<const float4*>(&hsrc[m0 + mi][kb * 4]);
#pragma unroll
        for (int offi = 0; offi < 4; offi++) {
            float4 wA = Wbase[((KB0 + kb) * 4 + offi) * 128 + 0];
            float4 wB = Wbase[((KB0 + kb) * 4 + offi) * 128 + 1];
#pragma unroll
            for (int mi = 0; mi < 4; mi++) {
                acc[mi][offi * 2 + 0] = dot4(hv[mi], wA, acc[mi][offi * 2 + 0]);
                acc[mi][offi * 2 + 1] = dot4(hv[mi], wB, acc[mi][offi * 2 + 1]);
            }
        }
    }
}

__global__ void __launch_bounds__(NTHR)
lstm_main(const float* __restrict__ hr, const float* __restrict__ glu,
          const float* __restrict__ wi0,
          const float* __restrict__ w1, const float* __restrict__ b1,
          const float* __restrict__ w2, const float* __restrict__ b2,
          float* __restrict__ out)
{
    __shared__ float h0s[2][MROWS][HID];
    __shared__ float h1s[2][MROWS][HID];
    __shared__ float hid_s[MROWS][64];

    const int tid  = threadIdx.x;
    const int mgrp = tid >> 6;        // 0..3  -> 4 batch rows each
    const int u2   = tid & 63;        // 0..63 -> 2 hidden units each
    const int m0   = mgrp * 4;
    const int B0   = blockIdx.x * MROWS;

    // zero h state (both buffers)
    for (int i = tid; i < MROWS * HID; i += NTHR) {
        (&h0s[0][0][0])[i] = 0.f; (&h0s[1][0][0])[i] = 0.f;
        (&h1s[0][0][0])[i] = 0.f; (&h1s[1][0][0])[i] = 0.f;
    }

    // per-thread constants: input-proj weights + fused biases for its 8 gates
    float wia[8], wib[8], bs0[8], bs1[8];
#pragma unroll
    for (int offi = 0; offi < 4; offi++)
#pragma unroll
        for (int uu = 0; uu < 2; uu++) {
            int g  = offi * 128 + u2 * 2 + uu;
            int gi = offi * 2 + uu;
            wia[gi] = wi0[g * 2 + 0];
            wib[gi] = wi0[g * 2 + 1];
            bs0[gi] = d_B0[g];
            bs1[gi] = d_B1[g];
        }

    float c0r[8], c1r[8];
#pragma unroll
    for (int i = 0; i < 8; i++) { c0r[i] = 0.f; c1r[i] = 0.f; }

    const float4* W0 = reinterpret_cast<const float4*>(d_WT0) + u2 * 2;
    const float4* W1 = reinterpret_cast<const float4*>(d_WT1) + u2 * 2;

    __syncthreads();

    int cur = 0;
    for (int t = 0; t < T_STEPS; t++) {
        const int nxt = cur ^ 1;
        float acc[4][8];

        // ---- layer 0: input projection init ----
#pragma unroll
        for (int mi = 0; mi < 4; mi++) {
            float xr = __ldg(&hr[(B0 + m0 + mi) * T_STEPS + t]);
            float xg = __ldg(&glu[(B0 + m0 + mi) * T_STEPS + t]);
#pragma unroll
            for (int gi = 0; gi < 8; gi++)
                acc[mi][gi] = fmaf(xr, wia[gi], fmaf(xg, wib[gi], bs0[gi]));
        }
        // ---- layer 0: recurrent GEMM (K=128) ----
        gemm128<0>(h0s[cur], m0, W0, acc);

        // ---- layer 0: LSTM cell, write h0[nxt] ----
#pragma unroll
        for (int mi = 0; mi < 4; mi++) {
            float2 hn;
#pragma unroll
            for (int uu = 0; uu < 2; uu++) {
                float i_ = sigmoidf_(acc[mi][0 + uu]);
                float f_ = sigmoidf_(acc[mi][2 + uu]);
                float g_ = tanhf(acc[mi][4 + uu]);
                float o_ = sigmoidf_(acc[mi][6 + uu]);
                int ci = mi * 2 + uu;
                float cn = fmaf(f_, c0r[ci], i_ * g_);
                c0r[ci] = cn;
                reinterpret_cast<float*>(&hn)[uu] = o_ * tanhf(cn);
            }
            *reinterpret_cast<float2*>(&h0s[nxt][m0 + mi][u2 * 2]) = hn;
        }

        __syncthreads();   // h0[nxt] visible to the whole m-group

        // ---- layer 1: K=256 ( [h0_t | h1_prev] @ [w_ih1 | w_hh1]^T ) ----
#pragma unroll
        for (int mi = 0; mi < 4; mi++)
#pragma unroll
            for (int gi = 0; gi < 8; gi++) acc[mi][gi] = bs1[gi];

        gemm128<0 >(h0s[nxt], m0, W1, acc);   // K[0:128)   with h0_t
        gemm128<32>(h1s[cur], m0, W1, acc);   // K[128:256) with h1_prev

        // ---- layer 1: LSTM cell, write h1[nxt] ----
#pragma unroll
        for (int mi = 0; mi < 4; mi++) {
            float2 hn;
#pragma unroll
            for (int uu = 0; uu < 2; uu++) {
                float i_ = sigmoidf_(acc[mi][0 + uu]);
                float f_ = sigmoidf_(acc[mi][2 + uu]);
                float g_ = tanhf(acc[mi][4 + uu]);
                float o_ = sigmoidf_(acc[mi][6 + uu]);
                int ci = mi * 2 + uu;
                float cn = fmaf(f_, c1r[ci], i_ * g_);
                c1r[ci] = cn;
                reinterpret_cast<float*>(&hn)[uu] = o_ * tanhf(cn);
            }
            *reinterpret_cast<float2*>(&h1s[nxt][m0 + mi][u2 * 2]) = hn;
        }
        cur = nxt;
        // the next iteration's post-layer0 __syncthreads orders these h1
        // writes before any thread reads h1s in the next layer-1 phase
    }

    __syncthreads();   // final h1 (in h1s[cur]) visible to all

    // ---- head: hidden = relu(h1 @ w1^T + b1) ----
    {
        int ff = tid & 63;
        int mq = tid >> 6;
#pragma unroll
        for (int j = 0; j < 4; j++) {
            int m = mq + j * 4;
            float s = b1[ff];
            const float* wrow = &w1[ff * HID];
#pragma unroll 4
            for (int k = 0; k < HID; k += 4) {
                float4 wv = *reinterpret_cast<const float4*>(&wrow[k]);
                float4 hv = *reinterpret_cast<const float4*>(&h1s[cur][m][k]);
                s = dot4(hv, wv, s);
            }
            hid_s[m][ff] = fmaxf(s, 0.f);
        }
    }
    __syncthreads();

    // ---- head: out = hidden @ w2^T + b2 ----
    if (tid < 32) {
        int m = tid >> 1, o = tid & 1;
        float s = b2[o];
#pragma unroll 8
        for (int k = 0; k < 64; k++)
            s = fmaf(hid_s[m][k], w2[o * 64 + k], s);
        out[(B0 + m) * 2 + o] = s;
    }
}

extern "C" void kernel_launch(void* const* d_in, const int* in_sizes, int n_in,
                              void* d_out, int out_size)
{
    const float* hr   = (const float*)d_in[0];   // hr_seq          [2048,512,1]
    const float* glu  = (const float*)d_in[1];   // glucose_context [2048,512,1]
    const float* wih0 = (const float*)d_in[2];   // [512,2]
    const float* whh0 = (const float*)d_in[3];   // [512,128]
    const float* bih0 = (const float*)d_in[4];   // [512]
    const float* bhh0 = (const float*)d_in[5];   // [512]
    const float* wih1 = (const float*)d_in[6];   // [512,128]
    const float* whh1 = (const float*)d_in[7];   // [512,128]
    const float* bih1 = (const float*)d_in[8];   // [512]
    const float* bhh1 = (const float*)d_in[9];   // [512]
    const float* w1   = (const float*)d_in[10];  // [64,128]
    const float* b1   = (const float*)d_in[11];  // [64]
    const float* w2   = (const float*)d_in[12];  // [2,64]
    const float* b2   = (const float*)d_in[13];  // [2]
    float* out = (float*)d_out;                  // [2048,2]

    prep_kernel<<<128, 256>>>(whh0, wih1, whh1, bih0, bhh0, bih1, bhh1);
    lstm_main<<<NCTA, NTHR>>>(hr, glu, wih0, w1, b1, w2, b2, out);
}

// round 2
// speedup vs baseline: 6.8260x; 6.8260x over previous
#include <cuda_runtime.h>
#include <cstdint>

// LSTMBaseline: 2-layer LSTM (B=2048, T=512, H=128, in=2) + MLP head -> [B,2]
// TF32 mma.sync version. 128 CTAs x 256 thr, M=16 batch rows/CTA, warps
// partition the 512 gate columns. Bias + input proj folded into K via
// constant columns. One __syncthreads per timestep.

#define T_STEPS 512
#define HID     128
#define MROWS   16
#define NCTA    128
#define NTHR    256
#define SSTR    148          // smem row stride in floats (bank-conflict-free)

// Prepacked weights in B-fragment order (tf32-rounded fp32).
// WP0: layer0, K extended to 144 (128 h + xr + xg + bias + pad): 64 nb * 9 kp * 32 lanes
// WP1: layer1, K = 128 (h0, w_ih1) + 144 (h1 + bias + pad): 64 nb * 17 kp * 32 lanes
__device__ float4 d_WP0[64 * 9 * 32];
__device__ float4 d_WP1[64 * 17 * 32];

__device__ __forceinline__ float tf32r(float x)
{
    uint32_t u;
    asm("cvt.rna.tf32.f32 %0, %1;" : "=r"(u) : "f"(x));
    return __uint_as_float(u);
}

// gate mapping: global n-column nbG*8 + (lane>>2)  ->  gate row g
__device__ __forceinline__ int gate_of(int nbG, int lane)
{
    int wv  = nbG >> 3;          // owning warp
    int nbl = nbG & 7;           // nb within warp
    int gt  = nbl >> 1;          // gate type 0..3 (i,f,g,o)
    int u   = wv * 16 + (nbl & 1) * 8 + (lane >> 2);
    return gt * 128 + u;
}

__global__ void prep_kernel(const float* __restrict__ w_hh0, const float* __restrict__ w_ih0,
                            const float* __restrict__ b_ih0, const float* __restrict__ b_hh0,
                            const float* __restrict__ w_ih1, const float* __restrict__ w_hh1,
                            const float* __restrict__ b_ih1, const float* __restrict__ b_hh1)
{
    int idx = blockIdx.x * blockDim.x + threadIdx.x;
    int l = idx & 31;
    int c = l & 3;

    if (idx < 64 * 9 * 32) {                     // ---- WP0 ----
        int r = idx >> 5;
        int kp = r % 9, nbG = r / 9;
        int g = gate_of(nbG, l);
        float v[4];
#pragma unroll
        for (int q = 0; q < 4; q++) {
            int k = kp * 16 + q * 4 + c;
            float x;
            if (k < 128)       x = w_hh0[g * 128 + k];
            else if (k == 128) x = w_ih0[g * 2 + 0];
            else if (k == 129) x = w_ih0[g * 2 + 1];
            else if (k == 130) x = b_ih0[g] + b_hh0[g];
            else               x = 0.f;
            v[q] = tf32r(x);
        }
        d_WP0[idx] = make_float4(v[0], v[1], v[2], v[3]);
    }
    int idx2 = idx - 64 * 9 * 32;
    if (idx2 >= 0 && idx2 < 64 * 17 * 32) {      // ---- WP1 ----
        int r = idx2 >> 5;
        int kp = r % 17, nbG = r / 17;
        int g = gate_of(nbG, l);
        float v[4];
#pragma unroll
        for (int q = 0; q < 4; q++) {
            float x;
            if (kp < 8) {                        // K 0..127 : w_ih1 (applied to h0_t)
                int k = kp * 16 + q * 4 + c;
                x = w_ih1[g * 128 + k];
            } else {                             // K 128..  : w_hh1 (h1) + bias col
                int k2 = (kp - 8) * 16 + q * 4 + c;
                if (k2 < 128)       x = w_hh1[g * 128 + k2];
                else if (k2 == 128) x = b_ih1[g] + b_hh1[g];
                else                x = 0.f;
            }
            v[q] = tf32r(x);
        }
        d_WP1[idx2] = make_float4(v[0], v[1], v[2], v[3]);
    }
}

__device__ __forceinline__ void mma8(float acc[4], const uint32_t a[4], uint32_t b0, uint32_t b1)
{
    asm volatile(
        "mma.sync.aligned.m16n8k8.row.col.f32.tf32.tf32.f32 "
        "{%0,%1,%2,%3}, {%4,%5,%6,%7}, {%8,%9}, {%0,%1,%2,%3};\n"
        : "+f"(acc[0]), "+f"(acc[1]), "+f"(acc[2]), "+f"(acc[3])
        : "r"(a[0]), "r"(a[1]), "r"(a[2]), "r"(a[3]), "r"(b0), "r"(b1));
}

__device__ __forceinline__ float sigf(float x)
{
    return __fdividef(1.f, 1.f + __expf(-x));
}
__device__ __forceinline__ float tanhf_(float x)
{
    return 1.f - __fdividef(2.f, __expf(2.f * x) + 1.f);
}

// KPN k-pairs of the GEMM; hb = A-tile base [16][SSTR]; wb = per-(warp,lane)
// weight base; NBSTR = kp-stride per nb in the packed array.
template <int KPN, int NBSTR>
__device__ __forceinline__ void gemm_run(const float* __restrict__ hb,
                                         const float4* __restrict__ wb,
                                         float acc[8][4], int r0, int c0)
{
    float4 Wc[8];
#pragma unroll
    for (int nb = 0; nb < 8; nb++) Wc[nb] = wb[nb * NBSTR * 32];
#pragma unroll
    for (int kp = 0; kp < KPN; kp++) {
        float4 Wn[8];
        if (kp + 1 < KPN) {
#pragma unroll
            for (int nb = 0; nb < 8; nb++) Wn[nb] = wb[(nb * NBSTR + kp + 1) * 32];
        }
        const float* arow = hb + kp * 16 + c0;
        uint32_t a[4];
        a[0] = __float_as_uint(arow[r0 * SSTR]);
        a[1] = __float_as_uint(arow[(r0 + 8) * SSTR]);
        a[2] = __float_as_uint(arow[r0 * SSTR + 4]);
        a[3] = __float_as_uint(arow[(r0 + 8) * SSTR + 4]);
#pragma unroll
        for (int nb = 0; nb < 8; nb++)
            mma8(acc[nb], a, __float_as_uint(Wc[nb].x), __float_as_uint(Wc[nb].y));
        a[0] = __float_as_uint(arow[r0 * SSTR + 8]);
        a[1] = __float_as_uint(arow[(r0 + 8) * SSTR + 8]);
        a[2] = __float_as_uint(arow[r0 * SSTR + 12]);
        a[3] = __float_as_uint(arow[(r0 + 8) * SSTR + 12]);
#pragma unroll
        for (int nb = 0; nb < 8; nb++)
            mma8(acc[nb], a, __float_as_uint(Wc[nb].z), __float_as_uint(Wc[nb].w));
        if (kp + 1 < KPN) {
#pragma unroll
            for (int nb = 0; nb < 8; nb++) Wc[nb] = Wn[nb];
        }
    }
}

// LSTM cell: acc holds 32 gate preacts in mma-D layout; thread-local i/f/g/o
// per unit. Writes tf32-rounded h to hdst (the [16][SSTR] dest tile).
__device__ __forceinline__ void cell_update(float acc[8][4], float* cst,
                                            float* __restrict__ hdst, int l, int w)
{
    int r0 = l >> 2, c2 = 2 * (l & 3);
#pragma unroll
    for (int hh = 0; hh < 2; hh++)
#pragma unroll
        for (int rg = 0; rg < 2; rg++) {
            int m = r0 + 8 * rg;
            float2 hv;
#pragma unroll
            for (int j = 0; j < 2; j++) {
                int idx = rg * 2 + j;
                float i_ = sigf(acc[0 + hh][idx]);
                float f_ = sigf(acc[2 + hh][idx]);
                float g_ = tanhf_(acc[4 + hh][idx]);
                float o_ = sigf(acc[6 + hh][idx]);
                int ci = (hh * 2 + rg) * 2 + j;
                float cv = fmaf(f_, cst[ci], i_ * g_);
                cst[ci] = cv;
                (&hv.x)[j] = tf32r(o_ * tanhf_(cv));
            }
            *reinterpret_cast<float2*>(hdst + m * SSTR + w * 16 + hh * 8 + c2) = hv;
        }
}

__global__ void __launch_bounds__(NTHR, 1)
lstm_main(const float* __restrict__ hr, const float* __restrict__ glu,
          const float* __restrict__ w1, const float* __restrict__ b1,
          const float* __restrict__ w2, const float* __restrict__ b2,
          float* __restrict__ out)
{
    __shared__ float h0e[2][MROWS][SSTR];   // cols: 0..127 h0 | 128 xr | 129 xg | 130 one | 0-pad
    __shared__ float h1e[2][MROWS][SSTR];   // cols: 0..127 h1 | 128 one | 0-pad
    __shared__ float hid_s[MROWS][64];

    const int tid = threadIdx.x;
    const int l = tid & 31, w = tid >> 5;
    const int r0 = l >> 2, c0 = l & 3;
    const int B0 = blockIdx.x * MROWS;

    // init state buffers (constant columns baked in)
    for (int i = tid; i < 2 * MROWS * SSTR; i += NTHR) {
        int col = i % SSTR;
        float v0 = (col == 130) ? 1.f : 0.f;
        float v1 = (col == 128) ? 1.f : 0.f;
        (&h0e[0][0][0])[i] = v0;
        (&h1e[0][0][0])[i] = v1;
    }
    __syncthreads();
    if (tid < 32) {     // x(t=0)
        int m = tid & 15;
        const float* src = (tid < 16) ? hr : glu;
        h0e[0][m][128 + (tid >> 4)] = tf32r(src[(B0 + m) * T_STEPS]);
    }

    float c0s[8], c1s[8];
#pragma unroll
    for (int i = 0; i < 8; i++) { c0s[i] = 0.f; c1s[i] = 0.f; }

    const float4* wb0 = d_WP0 + (w * 8 * 9) * 32 + l;
    const float4* wb1 = d_WP1 + (w * 8 * 17) * 32 + l;

    __syncthreads();

    int cur = 0;
    for (int t = 0; t < T_STEPS; t++) {
        const int nxt = cur ^ 1;
        float acc[8][4];
#pragma unroll
        for (int nb = 0; nb < 8; nb++)
#pragma unroll
            for (int q = 0; q < 4; q++) acc[nb][q] = 0.f;

        // ---- layer 0: gates = [h0_{t-1}, xr, xg, 1] @ W0ext^T ----
        gemm_run<9, 9>(&h0e[cur][0][0], wb0, acc, r0, c0);
        cell_update(acc, c0s, &h0e[nxt][0][0], l, w);

        // prefetch x(t+1) into the buffer layer0 reads next step
        if (tid < 32) {
            int m = tid & 15;
            const float* src = (tid < 16) ? hr : glu;
            float v = (t + 1 < T_STEPS) ? src[(B0 + m) * T_STEPS + t + 1] : 0.f;
            h0e[nxt][m][128 + (tid >> 4)] = tf32r(v);
        }

        __syncthreads();   // h0_t visible; single barrier per step

        // ---- layer 1: gates = [h0_t] @ Wih1^T + [h1_{t-1}, 1] @ Whh1ext^T ----
#pragma unroll
        for (int nb = 0; nb < 8; nb++)
#pragma unroll
            for (int q = 0; q < 4; q++) acc[nb][q] = 0.f;

        gemm_run<8, 17>(&h0e[nxt][0][0], wb1, acc, r0, c0);
        gemm_run<9, 17>(&h1e[cur][0][0], wb1 + 8 * 32, acc, r0, c0);
        cell_update(acc, c1s, &h1e[nxt][0][0], l, w);

        cur = nxt;
    }
    __syncthreads();   // final h1 (h1e[cur]) visible to all

    // ---- head: hidden = relu(h1 @ w1^T + b1) ----
    {
        int ff = tid & 63;
        int mq = tid >> 6;
#pragma unroll
        for (int j = 0; j < 4; j++) {
            int m = mq + j * 4;
            float s = b1[ff];
            const float* wrow = &w1[ff * HID];
#pragma unroll 4
            for (int k = 0; k < HID; k += 4) {
                float4 wv = *reinterpret_cast<const float4*>(&wrow[k]);
                float4 hv = *reinterpret_cast<const float4*>(&h1e[cur][m][k]);
                s = fmaf(hv.x, wv.x, s); s = fmaf(hv.y, wv.y, s);
                s = fmaf(hv.z, wv.z, s); s = fmaf(hv.w, wv.w, s);
            }
            hid_s[m][ff] = fmaxf(s, 0.f);
        }
    }
    __syncthreads();

    // ---- head: out = hidden @ w2^T + b2 ----
    if (tid < 32) {
        int m = tid >> 1, o = tid & 1;
        float s = b2[o];
#pragma unroll 8
        for (int k = 0; k < 64; k++)
            s = fmaf(hid_s[m][k], w2[o * 64 + k], s);
        out[(B0 + m) * 2 + o] = s;
    }
}

extern "C" void kernel_launch(void* const* d_in, const int* in_sizes, int n_in,
                              void* d_out, int out_size)
{
    const float* hr   = (const float*)d_in[0];   // hr_seq          [2048,512,1]
    const float* glu  = (const float*)d_in[1];   // glucose_context [2048,512,1]
    const float* wih0 = (const float*)d_in[2];   // [512,2]
    const float* whh0 = (const float*)d_in[3];   // [512,128]
    const float* bih0 = (const float*)d_in[4];   // [512]
    const float* bhh0 = (const float*)d_in[5];   // [512]
    const float* wih1 = (const float*)d_in[6];   // [512,128]
    const float* whh1 = (const float*)d_in[7];   // [512,128]
    const float* bih1 = (const float*)d_in[8];   // [512]
    const float* bhh1 = (const float*)d_in[9];   // [512]
    const float* w1   = (const float*)d_in[10];  // [64,128]
    const float* b1   = (const float*)d_in[11];  // [64]
    const float* w2   = (const float*)d_in[12];  // [2,64]
    const float* b2   = (const float*)d_in[13];  // [2]
    float* out = (float*)d_out;                  // [2048,2]

    prep_kernel<<<(64 * 9 * 32 + 64 * 17 * 32 + 255) / 256, 256>>>(
        whh0, wih0, bih0, bhh0, wih1, whh1, bih1, bhh1);
    lstm_main<<<NCTA, NTHR>>>(hr, glu, w1, b1, w2, b2, out);
}

// round 3
// speedup vs baseline: 11.7148x; 1.7162x over previous
#include <cuda_runtime.h>
#include <cuda_bf16.h>
#include <cstdint>

// LSTMBaseline: 2-layer LSTM (B=2048, T=512, H=128, in=2) + MLP head -> [B,2]
// bf16 mma.m16n8k16 version. 128 CTAs x 256 thr, M=16 batch rows/CTA.
// Layer-0 weights (+3/16 of layer-1) resident in smem; rest streamed from L2.
// Bias added in fp32 at accumulator init. One __syncthreads per timestep.

#define T_STEPS 512
#define HID     128
#define MROWS   16
#define NCTA    128
#define NTHR    256
#define HSTR    76            // h-row stride in bf16-pairs (bank-conflict-free)

#define L0KP    9             // layer0 k-chunks of 16 (128 h + xr,xg + pad)
#define L1KP    16            // layer1 k-chunks (128 h0 + 128 h1)
#define L1C     3             // layer1 k-chunks cached in smem

// Prepacked bf16 weight fragments (B-fragment order). uint2 = {b0,b1} regs.
__device__ uint2 d_WB0[64 * L0KP * 32];   // 147456 B
__device__ uint2 d_WB1[64 * L1KP * 32];   // 262144 B
__device__ float d_B0[512];
__device__ float d_B1[512];

// gate mapping: global n-column nbG*8 + (lane>>2) -> gate row g
__device__ __forceinline__ int gate_of(int nbG, int lane)
{
    int wv  = nbG >> 3;
    int nbl = nbG & 7;
    int gt  = nbl >> 1;                       // 0..3 = i,f,g,o
    int u   = wv * 16 + (nbl & 1) * 8 + (lane >> 2);
    return gt * 128 + u;
}

__device__ __forceinline__ uint32_t pack_bf2(float a, float b)
{
    __nv_bfloat162 p = __floats2bfloat162_rn(a, b);
    return *reinterpret_cast<uint32_t*>(&p);
}

__global__ void prep_kernel(const float* __restrict__ w_hh0, const float* __restrict__ w_ih0,
                            const float* __restrict__ b_ih0, const float* __restrict__ b_hh0,
                            const float* __restrict__ w_ih1, const float* __restrict__ w_hh1,
                            const float* __restrict__ b_ih1, const float* __restrict__ b_hh1)
{
    int idx = blockIdx.x * blockDim.x + threadIdx.x;
    int l = idx & 31, c = l & 3;
    int r = idx >> 5;

    if (idx < 64 * L0KP * 32) {               // ---- WB0 (layer0 ext: K=144) ----
        int kp = r % L0KP, nbG = r / L0KP;
        int g = gate_of(nbG, l);
        float v[4];
#pragma unroll
        for (int q = 0; q < 4; q++) {         // k = kp*16 + c*2 + (q&1) + (q>>1)*8
            int k = kp * 16 + (q >> 1) * 8 + c * 2 + (q & 1);
            float x;
            if (k < 128)       x = w_hh0[g * 128 + k];
            else if (k == 128) x = w_ih0[g * 2 + 0];
            else if (k == 129) x = w_ih0[g * 2 + 1];
            else               x = 0.f;
            v[q] = x;
        }
        d_WB0[idx] = make_uint2(pack_bf2(v[0], v[1]), pack_bf2(v[2], v[3]));
    }
    if (idx < 64 * L1KP * 32) {               // ---- WB1 (K=256: h0|h1) ----
        int kp = r % L1KP, nbG = r / L1KP;
        int g = gate_of(nbG, l);
        float v[4];
#pragma unroll
        for (int q = 0; q < 4; q++) {
            int kk = (kp & 7) * 16 + (q >> 1) * 8 + c * 2 + (q & 1);
            v[q] = (kp < 8) ? w_ih1[g * 128 + kk] : w_hh1[g * 128 + kk];
        }
        d_WB1[idx] = make_uint2(pack_bf2(v[0], v[1]), pack_bf2(v[2], v[3]));
    }
    if (idx < 512) {
        d_B0[idx] = b_ih0[idx] + b_hh0[idx];
        d_B1[idx] = b_ih1[idx] + b_hh1[idx];
    }
}

__device__ __forceinline__ void mma16(float acc[4], uint32_t a0, uint32_t a1,
                                      uint32_t a2, uint32_t a3, uint32_t b0, uint32_t b1)
{
    asm volatile(
        "mma.sync.aligned.m16n8k16.row.col.f32.bf16.bf16.f32 "
        "{%0,%1,%2,%3}, {%4,%5,%6,%7}, {%8,%9}, {%0,%1,%2,%3};\n"
        : "+f"(acc[0]), "+f"(acc[1]), "+f"(acc[2]), "+f"(acc[3])
        : "r"(a0), "r"(a1), "r"(a2), "r"(a3), "r"(b0), "r"(b1));
}

__device__ __forceinline__ float sigf(float x)
{
    return __fdividef(1.f, 1.f + __expf(-x));
}
__device__ __forceinline__ float tanhf_(float x)
{
    return 1.f - __fdividef(2.f, __expf(2.f * x) + 1.f);
}

// h: buffer base pre-offset by c0 (bf16-pair units). ws: per-lane smem weights.
template <int KPN, int KSTR>
__device__ __forceinline__ void gemm_smem(const uint32_t* __restrict__ h,
                                          const uint2* __restrict__ ws,
                                          float acc[8][4], int r0, int kp0)
{
#pragma unroll
    for (int kp = 0; kp < KPN; kp++) {
        const uint32_t* ar = h + (kp0 + kp) * 8;
        uint32_t a0 = ar[r0 * HSTR],     a1 = ar[(r0 + 8) * HSTR];
        uint32_t a2 = ar[r0 * HSTR + 4], a3 = ar[(r0 + 8) * HSTR + 4];
#pragma unroll
        for (int nb = 0; nb < 8; nb++) {
            uint2 b = ws[(nb * KSTR + kp) * 32];
            mma16(acc[nb], a0, a1, a2, a3, b.x, b.y);
        }
    }
}

// Global-weight variant with double-buffered prefetch.
template <int KPN, int KSTR>
__device__ __forceinline__ void gemm_glob(const uint32_t* __restrict__ h,
                                          const uint2* __restrict__ wg,
                                          float acc[8][4], int r0, int kp0)
{
    uint2 Wc[8];
#pragma unroll
    for (int nb = 0; nb < 8; nb++) Wc[nb] = __ldg(&wg[(nb * KSTR) * 32]);
#pragma unroll
    for (int kp = 0; kp < KPN; kp++) {
        uint2 Wn[8];
        if (kp + 1 < KPN) {
#pragma unroll
            for (int nb = 0; nb < 8; nb++) Wn[nb] = __ldg(&wg[(nb * KSTR + kp + 1) * 32]);
        }
        const uint32_t* ar = h + (kp0 + kp) * 8;
        uint32_t a0 = ar[r0 * HSTR],     a1 = ar[(r0 + 8) * HSTR];
        uint32_t a2 = ar[r0 * HSTR + 4], a3 = ar[(r0 + 8) * HSTR + 4];
#pragma unroll
        for (int nb = 0; nb < 8; nb++)
            mma16(acc[nb], a0, a1, a2, a3, Wc[nb].x, Wc[nb].y);
        if (kp + 1 < KPN) {
#pragma unroll
            for (int nb = 0; nb < 8; nb++) Wc[nb] = Wn[nb];
        }
    }
}

__device__ __forceinline__ void acc_init(float acc[8][4], const float* bs)
{
#pragma unroll
    for (int nb = 0; nb < 8; nb++) {
        acc[nb][0] = bs[2 * nb];     acc[nb][1] = bs[2 * nb + 1];
        acc[nb][2] = bs[2 * nb];     acc[nb][3] = bs[2 * nb + 1];
    }
}

__device__ __forceinline__ void cell_update(float acc[8][4], float* cst,
                                            uint32_t* __restrict__ hdst, int l, int w)
{
    int r0 = l >> 2, c = l & 3;
#pragma unroll
    for (int hh = 0; hh < 2; hh++)
#pragma unroll
        for (int rg = 0; rg < 2; rg++) {
            int m = r0 + 8 * rg;
            float hv[2];
#pragma unroll
            for (int j = 0; j < 2; j++) {
                int idx = rg * 2 + j;
                float i_ = sigf(acc[0 + hh][idx]);
                float f_ = sigf(acc[2 + hh][idx]);
                float g_ = tanhf_(acc[4 + hh][idx]);
                float o_ = sigf(acc[6 + hh][idx]);
                int ci = (hh * 2 + rg) * 2 + j;
                float cv = fmaf(f_, cst[ci], i_ * g_);
                cst[ci] = cv;
                hv[j] = o_ * tanhf_(cv);
            }
            hdst[m * HSTR + w * 8 + hh * 4 + c] = pack_bf2(hv[0], hv[1]);
        }
}

// dynamic smem: sw0 147456 | sw1 49152 | h0e 9728 | h1e 9728  = 216064 B
#define SW0_ELEMS (64 * L0KP * 32)
#define SW1_ELEMS (64 * L1C * 32)
#define SMEM_SZ   (SW0_ELEMS * 8 + SW1_ELEMS * 8 + 2 * 2 * MROWS * HSTR * 4)

__global__ void __launch_bounds__(NTHR, 1)
lstm_main(const float* __restrict__ hr, const float* __restrict__ glu,
          const float* __restrict__ w1, const float* __restrict__ b1,
          const float* __restrict__ w2, const float* __restrict__ b2,
          float* __restrict__ out)
{
    extern __shared__ char smem_raw[];
    uint2*     sw0 = reinterpret_cast<uint2*>(smem_raw);
    uint2*     sw1 = reinterpret_cast<uint2*>(smem_raw + SW0_ELEMS * 8);
    uint32_t*  h0e = reinterpret_cast<uint32_t*>(smem_raw + SW0_ELEMS * 8 + SW1_ELEMS * 8);
    uint32_t*  h1e = h0e + 2 * MROWS * HSTR;
    float*     hid_s = reinterpret_cast<float*>(smem_raw);   // overlay (after final sync)

    const int tid = threadIdx.x;
    const int l = tid & 31, w = tid >> 5;
    const int r0 = l >> 2, c0 = l & 3;
    const int B0 = blockIdx.x * MROWS;

    // ---- load resident weights into smem ----
    for (int i = tid; i < SW0_ELEMS; i += NTHR) sw0[i] = d_WB0[i];
    for (int i = tid; i < SW1_ELEMS; i += NTHR) {
        int ll = i & 31, rr = i >> 5;
        int kp = rr % L1C, nbG = rr / L1C;
        sw1[i] = d_WB1[(nbG * L1KP + kp) * 32 + ll];
    }
    // ---- init h buffers ----
    for (int i = tid; i < 2 * MROWS * HSTR; i += NTHR) { h0e[i] = 0u; h1e[i] = 0u; }
    __syncthreads();
    if (tid < MROWS) {        // x(t=0) -> pair 64 of h0e buffer 0
        float xr = hr[(B0 + tid) * T_STEPS];
        float xg = glu[(B0 + tid) * T_STEPS];
        h0e[tid * HSTR + 64] = pack_bf2(xr, xg);
    }

    // ---- fp32 biases for this thread's 16 gate columns ----
    float bs0[16], bs1[16];
#pragma unroll
    for (int nb = 0; nb < 8; nb++)
#pragma unroll
        for (int j = 0; j < 2; j++) {
            int g = (nb >> 1) * 128 + w * 16 + (nb & 1) * 8 + 2 * c0 + j;
            bs0[2 * nb + j] = d_B0[g];
            bs1[2 * nb + j] = d_B1[g];
        }

    float c0s[8], c1s[8];
#pragma unroll
    for (int i = 0; i < 8; i++) { c0s[i] = 0.f; c1s[i] = 0.f; }

    const uint2* ws0 = sw0 + (w * 8 * L0KP) * 32 + l;
    const uint2* ws1 = sw1 + (w * 8 * L1C) * 32 + l;
    const uint2* wg1 = d_WB1 + (w * 8 * L1KP + L1C) * 32 + l;   // streamed part

    __syncthreads();

    int cur = 0;
    for (int t = 0; t < T_STEPS; t++) {
        const int nxt = cur ^ 1;
        uint32_t* h0n = h0e + nxt * MROWS * HSTR;
        float acc[8][4];

        // ---- layer 0: gates = [h0_{t-1}, xr, xg] @ W0ext^T + b0 ----
        acc_init(acc, bs0);
        gemm_smem<L0KP, L0KP>(h0e + cur * MROWS * HSTR + c0, ws0, acc, r0, 0);
        cell_update(acc, c0s, h0n, l, w);

        if (tid < MROWS) {    // prefetch x(t+1)
            float xr = 0.f, xg = 0.f;
            if (t + 1 < T_STEPS) {
                xr = hr[(B0 + tid) * T_STEPS + t + 1];
                xg = glu[(B0 + tid) * T_STEPS + t + 1];
            }
            h0n[tid * HSTR + 64] = pack_bf2(xr, xg);
        }

        __syncthreads();      // h0_t visible; single barrier per step

        // ---- layer 1: gates = h0_t @ Wih1^T + h1_{t-1} @ Whh1^T + b1 ----
        acc_init(acc, bs1);
        gemm_smem<L1C, L1C>(h0n + c0, ws1, acc, r0, 0);                       // kp 0..2
        gemm_glob<8 - L1C, L1KP>(h0n + c0, wg1, acc, r0, L1C);                // kp 3..7
        gemm_glob<8, L1KP>(h1e + cur * MROWS * HSTR + c0,
                           wg1 + (8 - L1C) * 32, acc, r0, 0);                 // kp 8..15
        cell_update(acc, c1s, h1e + nxt * MROWS * HSTR, l, w);

        cur = nxt;
    }
    __syncthreads();          // final h1 visible; weights in smem now dead

    // ---- head: hidden = relu(h1 @ w1^T + b1) ----
    {
        int ff = tid & 63;
        int mq = tid >> 6;
        const float2* w1p = reinterpret_cast<const float2*>(w1 + ff * HID);
#pragma unroll
        for (int j = 0; j < 4; j++) {
            int m = mq + j * 4;
            float s = b1[ff];
            const uint32_t* hp = h1e + cur * MROWS * HSTR + m * HSTR;
#pragma unroll 8
            for (int p = 0; p < 64; p++) {
                float2 hv = __bfloat1622float2(
                    *reinterpret_cast<const __nv_bfloat162*>(&hp[p]));
                float2 wv = w1p[p];
                s = fmaf(hv.x, wv.x, s);
                s = fmaf(hv.y, wv.y, s);
            }
            hid_s[m * 64 + ff] = fmaxf(s, 0.f);
        }
    }
    __syncthreads();

    // ---- head: out = hidden @ w2^T + b2 ----
    if (tid < 32) {
        int m = tid >> 1, o = tid & 1;
        float s = b2[o];
#pragma unroll 8
        for (int k = 0; k < 64; k++)
            s = fmaf(hid_s[m * 64 + k], w2[o * 64 + k], s);
        out[(B0 + m) * 2 + o] = s;
    }
}

extern "C" void kernel_launch(void* const* d_in, const int* in_sizes, int n_in,
                              void* d_out, int out_size)
{
    const float* hr   = (const float*)d_in[0];
    const float* glu  = (const float*)d_in[1];
    const float* wih0 = (const float*)d_in[2];
    const float* whh0 = (const float*)d_in[3];
    const float* bih0 = (const float*)d_in[4];
    const float* bhh0 = (const float*)d_in[5];
    const float* wih1 = (const float*)d_in[6];
    const float* whh1 = (const float*)d_in[7];
    const float* bih1 = (const float*)d_in[8];
    const float* bhh1 = (const float*)d_in[9];
    const float* w1   = (const float*)d_in[10];
    const float* b1   = (const float*)d_in[11];
    const float* w2   = (const float*)d_in[12];
    const float* b2   = (const float*)d_in[13];
    float* out = (float*)d_out;

    cudaFuncSetAttribute(lstm_main, cudaFuncAttributeMaxDynamicSharedMemorySize, SMEM_SZ);

    prep_kernel<<<(64 * L1KP * 32 + NTHR - 1) / NTHR, NTHR>>>(
        whh0, wih0, bih0, bhh0, wih1, whh1, bih1, bhh1);
    lstm_main<<<NCTA, NTHR, SMEM_SZ>>>(hr, glu, w1, b1, w2, b2, out);
}

// round 4
// speedup vs baseline: 14.6413x; 1.2498x over previous
#include <cuda_runtime.h>
#include <cuda_bf16.h>
#include <cstdint>

// LSTMBaseline: 2-layer LSTM (B=2048, T=512, H=128, in=2) + MLP head -> [B,2]
// bf16 mma.m16n8k16, 128 CTAs x 512 thr (16 warps), M=16 batch rows/CTA.
// Single barrier per step: layer1(t) and layer0(t+1) gemms fused into one
// phase (both depend only on h0_t, h1_{t-1}, x_{t+1}). tanh.approx activations.
// Layer0 weights + 3/16 of layer1 resident in smem, rest streamed from L2.

#define T_STEPS 512
#define HID     128
#define MROWS   16
#define NCTA    128
#define NTHR    512
#define HSTR    76            // h-row stride in bf16-pairs (conflict-free: r0*76%32 distinct)

#define L0KP    9             // layer0 k-chunks of 16 (128 h + xr,xg + pad)
#define L1KP    16            // layer1 k-chunks (128 h0 | 128 h1)
#define L1C     3             // layer1 k-chunks cached in smem

// Prepacked bf16 B-fragments. Index: ((w*4+gt)*KP + kp)*32 + lane
__device__ uint2 d_WB0[16 * 4 * L0KP * 32];   // 147456 B
__device__ uint2 d_WB1[16 * 4 * L1KP * 32];   // 262144 B
__device__ float d_B0[512];
__device__ float d_B1[512];

__device__ __forceinline__ uint32_t pack_bf2(float a, float b)
{
    __nv_bfloat162 p = __floats2bfloat162_rn(a, b);
    return *reinterpret_cast<uint32_t*>(&p);
}

__global__ void prep_kernel(const float* __restrict__ w_hh0, const float* __restrict__ w_ih0,
                            const float* __restrict__ b_ih0, const float* __restrict__ b_hh0,
                            const float* __restrict__ w_ih1, const float* __restrict__ w_hh1,
                            const float* __restrict__ b_ih1, const float* __restrict__ b_hh1)
{
    int idx = blockIdx.x * blockDim.x + threadIdx.x;
    int l = idx & 31, c = l & 3;
    int r = idx >> 5;

    if (idx < 16 * 4 * L0KP * 32) {           // ---- WB0 ----
        int kp = r % L0KP, wg = r / L0KP;
        int g = (wg & 3) * 128 + (wg >> 2) * 8 + (l >> 2);
        float v[4];
#pragma unroll
        for (int q = 0; q < 4; q++) {
            int k = kp * 16 + (q >> 1) * 8 + c * 2 + (q & 1);
            float x;
            if (k < 128)       x = w_hh0[g * 128 + k];
            else if (k == 128) x = w_ih0[g * 2 + 0];
            else if (k == 129) x = w_ih0[g * 2 + 1];
            else               x = 0.f;
            v[q] = x;
        }
        d_WB0[idx] = make_uint2(pack_bf2(v[0], v[1]), pack_bf2(v[2], v[3]));
    }
    if (idx < 16 * 4 * L1KP * 32) {           // ---- WB1 ----
        int kp = r % L1KP, wg = r / L1KP;
        int g = (wg & 3) * 128 + (wg >> 2) * 8 + (l >> 2);
        float v[4];
#pragma unroll
        for (int q = 0; q < 4; q++) {
            int kk = (kp & 7) * 16 + (q >> 1) * 8 + c * 2 + (q & 1);
            v[q] = (kp < 8) ? w_ih1[g * 128 + kk] : w_hh1[g * 128 + kk];
        }
        d_WB1[idx] = make_uint2(pack_bf2(v[0], v[1]), pack_bf2(v[2], v[3]));
    }
    if (idx < 512) {
        d_B0[idx] = b_ih0[idx] + b_hh0[idx];
        d_B1[idx] = b_ih1[idx] + b_hh1[idx];
    }
}

__device__ __forceinline__ void mma16(float acc[4], uint32_t a0, uint32_t a1,
                                      uint32_t a2, uint32_t a3, uint32_t b0, uint32_t b1)
{
    asm volatile(
        "mma.sync.aligned.m16n8k16.row.col.f32.bf16.bf16.f32 "
        "{%0,%1,%2,%3}, {%4,%5,%6,%7}, {%8,%9}, {%0,%1,%2,%3};\n"
        : "+f"(acc[0]), "+f"(acc[1]), "+f"(acc[2]), "+f"(acc[3])
        : "r"(a0), "r"(a1), "r"(a2), "r"(a3), "r"(b0), "r"(b1));
}

__device__ __forceinline__ float tanha(float x)
{
    float y;
    asm("tanh.approx.f32 %0, %1;" : "=f"(y) : "f"(x));
    return y;
}
__device__ __forceinline__ float sigf(float x)
{
    return fmaf(tanha(0.5f * x), 0.5f, 0.5f);
}

// One k16 chunk: A-frags from ar (pre-offset by c0), 4 gate-type mmas.
__device__ __forceinline__ void gstep(float acc[4][4], const uint32_t* __restrict__ ar,
                                      int r0, const uint2 b[4])
{
    uint32_t a0 = ar[r0 * HSTR],     a1 = ar[(r0 + 8) * HSTR];
    uint32_t a2 = ar[r0 * HSTR + 4], a3 = ar[(r0 + 8) * HSTR + 4];
#pragma unroll
    for (int gt = 0; gt < 4; gt++)
        mma16(acc[gt], a0, a1, a2, a3, b[gt].x, b[gt].y);
}

__device__ __forceinline__ void acc_init(float acc[4][4], const float* bs)
{
#pragma unroll
    for (int gt = 0; gt < 4; gt++) {
        acc[gt][0] = bs[gt * 2];  acc[gt][1] = bs[gt * 2 + 1];
        acc[gt][2] = bs[gt * 2];  acc[gt][3] = bs[gt * 2 + 1];
    }
}

// acc[gt][rg*2+j]: batch row r0+8rg, unit w*8 + 2c0+j. cs[rg*2+j] cell state.
__device__ __forceinline__ void cell(const float acc[4][4], float* cs,
                                     uint32_t* __restrict__ hdst, int r0, int c0, int w)
{
#pragma unroll
    for (int rg = 0; rg < 2; rg++) {
        float hv[2];
#pragma unroll
        for (int j = 0; j < 2; j++) {
            int idx = rg * 2 + j;
            float i_ = sigf(acc[0][idx]);
            float f_ = sigf(acc[1][idx]);
            float g_ = tanha(acc[2][idx]);
            float o_ = sigf(acc[3][idx]);
            float cv = fmaf(f_, cs[idx], i_ * g_);
            cs[idx] = cv;
            hv[j] = o_ * tanha(cv);
        }
        hdst[(r0 + 8 * rg) * HSTR + w * 4 + c0] = pack_bf2(hv[0], hv[1]);
    }
}

#define SW0_ELEMS (16 * 4 * L0KP * 32)            // 18432 uint2
#define SW1_ELEMS (16 * 4 * L1C * 32)             // 6144 uint2
#define HBUF      (2 * MROWS * HSTR)              // uint32 per (layer) ping-pong pair
#define SMEM_SZ   (SW0_ELEMS * 8 + SW1_ELEMS * 8 + 2 * HBUF * 4)

__global__ void __launch_bounds__(NTHR, 1)
lstm_main(const float* __restrict__ hr, const float* __restrict__ glu,
          const float* __restrict__ w1, const float* __restrict__ b1,
          const float* __restrict__ w2, const float* __restrict__ b2,
          float* __restrict__ out)
{
    extern __shared__ char smem_raw[];
    uint2*    sw0 = reinterpret_cast<uint2*>(smem_raw);
    uint2*    sw1 = reinterpret_cast<uint2*>(smem_raw + SW0_ELEMS * 8);
    uint32_t* h0e = reinterpret_cast<uint32_t*>(smem_raw + SW0_ELEMS * 8 + SW1_ELEMS * 8);
    uint32_t* h1e = h0e + HBUF;
    float*    hid_s = reinterpret_cast<float*>(smem_raw);   // overlay, used after loop

    const int tid = threadIdx.x;
    const int l = tid & 31, w = tid >> 5;
    const int r0 = l >> 2, c0 = l & 3;
    const int B0 = blockIdx.x * MROWS;

    // ---- load resident weights ----
    for (int i = tid; i < SW0_ELEMS; i += NTHR) sw0[i] = d_WB0[i];
    for (int i = tid; i < SW1_ELEMS; i += NTHR) {
        int ll = i & 31, rr = i >> 5;
        int kp = rr % L1C, wg = rr / L1C;
        sw1[i] = d_WB1[(wg * L1KP + kp) * 32 + ll];
    }
    // ---- zero h buffers (both layers, both phases, incl. pad/x slots) ----
    for (int i = tid; i < HBUF; i += NTHR) { h0e[i] = 0u; h1e[i] = 0u; }
    __syncthreads();
    if (tid < MROWS)    // x_0 -> pair 64 of h0e phase 0
        h0e[tid * HSTR + 64] = pack_bf2(hr[(B0 + tid) * T_STEPS], glu[(B0 + tid) * T_STEPS]);

    // ---- per-thread fp32 biases ----
    float bs0[8], bs1[8];
#pragma unroll
    for (int gt = 0; gt < 4; gt++)
#pragma unroll
        for (int j = 0; j < 2; j++) {
            int g = gt * 128 + w * 8 + 2 * c0 + j;
            bs0[gt * 2 + j] = d_B0[g];
            bs1[gt * 2 + j] = d_B1[g];
        }

    float cs0[4] = {0.f, 0.f, 0.f, 0.f};
    float cs1[4] = {0.f, 0.f, 0.f, 0.f};

    const uint2* ws0 = sw0 + (w * 4 * L0KP) * 32 + l;
    const uint2* ws1 = sw1 + (w * 4 * L1C) * 32 + l;
    const uint2* wg1 = d_WB1 + (w * 4 * L1KP) * 32 + l;

    __syncthreads();

    // ---- prologue: h0_0 = cell0([h0=0, x_0]) ----
    {
        float acc0[4][4];
        acc_init(acc0, bs0);
        const uint32_t* h0c = h0e + c0;
#pragma unroll
        for (int kp = 0; kp < L0KP; kp++) {
            uint2 b[4];
#pragma unroll
            for (int gt = 0; gt < 4; gt++) b[gt] = ws0[(gt * L0KP + kp) * 32];
            gstep(acc0, h0c + kp * 8, r0, b);
        }
        cell(acc0, cs0, h0e + MROWS * HSTR, r0, c0, w);
        if (tid < MROWS)    // x_1 -> phase-1 x slot
            h0e[MROWS * HSTR + tid * HSTR + 64] =
                pack_bf2(hr[(B0 + tid) * T_STEPS + 1], glu[(B0 + tid) * T_STEPS + 1]);
        __syncthreads();
    }

    int cur = 1;
#pragma unroll 1
    for (int t = 0; t < T_STEPS; t++) {
        const int nxt = cur ^ 1;
        const uint32_t* h0c = h0e + cur * MROWS * HSTR + c0;   // h0_t (+ x_{t+1})
        const uint32_t* h1c = h1e + cur * MROWS * HSTR + c0;   // h1_{t-1}
        float acc1[4][4], acc0[4][4];
        acc_init(acc1, bs1);
        acc_init(acc0, bs0);

        // ---- layer1 gates: smem kp 0..2 ----
#pragma unroll
        for (int kp = 0; kp < L1C; kp++) {
            uint2 b[4];
#pragma unroll
            for (int gt = 0; gt < 4; gt++) b[gt] = ws1[(gt * L1C + kp) * 32];
            gstep(acc1, h0c + kp * 8, r0, b);
        }
        // ---- layer1 gates: streamed kp 3..15 (h0 part then h1 part) ----
        {
            uint2 bc[4], bn[4];
#pragma unroll
            for (int gt = 0; gt < 4; gt++) bc[gt] = __ldg(&wg1[(gt * L1KP + L1C) * 32]);
#pragma unroll
            for (int kp = L1C; kp < L1KP; kp++) {
                if (kp + 1 < L1KP) {
#pragma unroll
                    for (int gt = 0; gt < 4; gt++)
                        bn[gt] = __ldg(&wg1[(gt * L1KP + kp + 1) * 32]);
                }
                const uint32_t* ar = (kp < 8) ? (h0c + kp * 8) : (h1c + (kp - 8) * 8);
                gstep(acc1, ar, r0, bc);
                if (kp + 1 < L1KP) {
#pragma unroll
                    for (int gt = 0; gt < 4; gt++) bc[gt] = bn[gt];
                }
            }
        }
        // ---- layer0 gates for t+1: smem kp 0..8 over [h0_t, x_{t+1}] ----
#pragma unroll
        for (int kp = 0; kp < L0KP; kp++) {
            uint2 b[4];
#pragma unroll
            for (int gt = 0; gt < 4; gt++) b[gt] = ws0[(gt * L0KP + kp) * 32];
            gstep(acc0, h0c + kp * 8, r0, b);
        }

        // ---- both cells -> phase nxt ----
        cell(acc1, cs1, h1e + nxt * MROWS * HSTR, r0, c0, w);   // h1_t
        cell(acc0, cs0, h0e + nxt * MROWS * HSTR, r0, c0, w);   // h0_{t+1}

        if (tid < MROWS && t + 2 < T_STEPS)   // x_{t+2} -> phase nxt x slot
            h0e[nxt * MROWS * HSTR + tid * HSTR + 64] =
                pack_bf2(hr[(B0 + tid) * T_STEPS + t + 2],
                         glu[(B0 + tid) * T_STEPS + t + 2]);

        __syncthreads();
        cur = nxt;
    }
    // final h1_511 is in h1e phase cur. Weights in smem now dead.

    // ---- head: hidden = relu(h1 @ w1^T + b1) ----
    if (tid < 256) {
        int ff = tid & 63;
        int mq = tid >> 6;
        const float2* w1p = reinterpret_cast<const float2*>(w1 + ff * HID);
#pragma unroll
        for (int j = 0; j < 4; j++) {
            int m = mq + j * 4;
            float s = b1[ff];
            const uint32_t* hp = h1e + cur * MROWS * HSTR + m * HSTR;
#pragma unroll 8
            for (int p = 0; p < 64; p++) {
                float2 hv = __bfloat1622float2(
                    *reinterpret_cast<const __nv_bfloat162*>(&hp[p]));
                float2 wv = w1p[p];
                s = fmaf(hv.x, wv.x, s);
                s = fmaf(hv.y, wv.y, s);
            }
            hid_s[m * 64 + ff] = fmaxf(s, 0.f);
        }
    }
    __syncthreads();

    // ---- head: out = hidden @ w2^T + b2 ----
    if (tid < 32) {
        int m = tid >> 1, o = tid & 1;
        float s = b2[o];
#pragma unroll 8
        for (int k = 0; k < 64; k++)
            s = fmaf(hid_s[m * 64 + k], w2[o * 64 + k], s);
        out[(B0 + m) * 2 + o] = s;
    }
}

extern "C" void kernel_launch(void* const* d_in, const int* in_sizes, int n_in,
                              void* d_out, int out_size)
{
    const float* hr   = (const float*)d_in[0];
    const float* glu  = (const float*)d_in[1];
    const float* wih0 = (const float*)d_in[2];
    const float* whh0 = (const float*)d_in[3];
    const float* bih0 = (const float*)d_in[4];
    const float* bhh0 = (const float*)d_in[5];
    const float* wih1 = (const float*)d_in[6];
    const float* whh1 = (const float*)d_in[7];
    const float* bih1 = (const float*)d_in[8];
    const float* bhh1 = (const float*)d_in[9];
    const float* w1   = (const float*)d_in[10];
    const float* b1   = (const float*)d_in[11];
    const float* w2   = (const float*)d_in[12];
    const float* b2   = (const float*)d_in[13];
    float* out = (float*)d_out;

    cudaFuncSetAttribute(lstm_main, cudaFuncAttributeMaxDynamicSharedMemorySize, SMEM_SZ);

    prep_kernel<<<128, 256>>>(whh0, wih0, bih0, bhh0, wih1, whh1, bih1, bhh1);
    lstm_main<<<NCTA, NTHR, SMEM_SZ>>>(hr, glu, w1, b1, w2, b2, out);
}

// round 5
// speedup vs baseline: 15.4653x; 1.0563x over previous
#include <cuda_runtime.h>
#include <cuda_bf16.h>
#include <cstdint>

// LSTMBaseline: 2-layer LSTM (B=2048, T=512, H=128, in=2) + MLP head -> [B,2]
// bf16 mma.m16n8k16, 128 CTAs x 512 thr, M=16 batch rows/CTA.
// ldmatrix.x4 A-loads; h0 A-fragments shared between layer1/layer0 gemms;
// weights packed gate-pair x lane-contiguous uint4 (LDS.128/LDG.128).
// Single barrier per step; tanh.approx activations.

#define T_STEPS 512
#define HID     128
#define MROWS   16
#define NCTA    128
#define NTHR    512
#define HSTR    76            // h-row stride in bf16-pairs; 304B: ldmatrix conflict-free
#define PB      (MROWS * HSTR * 4)   // phase stride in bytes (4864, 16B aligned)

#define L0KP    9             // layer0 k-chunks (128 h + xr,xg + pad)
#define L1KP    16            // layer1 k-chunks (128 h0 | 128 h1)
#define L1C     3             // layer1 k-chunks cached in smem
#define NSTREAM (L1KP - L1C)  // 13 streamed k-chunks

// uint4 = {gtA.b0, gtA.b1, gtB.b0, gtB.b1}, gtA=2p, gtB=2p+1
// index: ((w*KP + kp)*2 + p)*32 + lane
__device__ uint4 d_WB0u[16 * L0KP * 2 * 32];   // 147456 B
__device__ uint4 d_WB1u[16 * L1KP * 2 * 32];   // 262144 B
__device__ float d_B0[512];
__device__ float d_B1[512];

__device__ __forceinline__ uint32_t pack_bf2(float a, float b)
{
    __nv_bfloat162 p = __floats2bfloat162_rn(a, b);
    return *reinterpret_cast<uint32_t*>(&p);
}

// B-fragment value for (gate gt, lane l, k-chunk element q) of a 128-col matrix
__device__ __forceinline__ float wval0(const float* w_hh0, const float* w_ih0,
                                       int g, int kp, int c, int q)
{
    int k = kp * 16 + (q >> 1) * 8 + c * 2 + (q & 1);
    if (k < 128)  return w_hh0[g * 128 + k];
    if (k == 128) return w_ih0[g * 2 + 0];
    if (k == 129) return w_ih0[g * 2 + 1];
    return 0.f;
}

__global__ void prep_kernel(const float* __restrict__ w_hh0, const float* __restrict__ w_ih0,
                            const float* __restrict__ b_ih0, const float* __restrict__ b_hh0,
                            const float* __restrict__ w_ih1, const float* __restrict__ w_hh1,
                            const float* __restrict__ b_ih1, const float* __restrict__ b_hh1)
{
    int idx = blockIdx.x * blockDim.x + threadIdx.x;
    int l = idx & 31, c = l & 3;
    int r = idx >> 5;

    if (idx < 16 * L0KP * 2 * 32) {           // ---- WB0 ----
        int p = r & 1, rr = r >> 1;
        int kp = rr % L0KP, w = rr / L0KP;
        int n = w * 8 + (l >> 2);
        int gA = (2 * p) * 128 + n, gB = (2 * p + 1) * 128 + n;
        d_WB0u[idx] = make_uint4(
            pack_bf2(wval0(w_hh0, w_ih0, gA, kp, c, 0), wval0(w_hh0, w_ih0, gA, kp, c, 1)),
            pack_bf2(wval0(w_hh0, w_ih0, gA, kp, c, 2), wval0(w_hh0, w_ih0, gA, kp, c, 3)),
            pack_bf2(wval0(w_hh0, w_ih0, gB, kp, c, 0), wval0(w_hh0, w_ih0, gB, kp, c, 1)),
            pack_bf2(wval0(w_hh0, w_ih0, gB, kp, c, 2), wval0(w_hh0, w_ih0, gB, kp, c, 3)));
    }
    if (idx < 16 * L1KP * 2 * 32) {           // ---- WB1 ----
        int p = r & 1, rr = r >> 1;
        int kp = rr % L1KP, w = rr / L1KP;
        int n = w * 8 + (l >> 2);
        const float* src = (kp < 8) ? w_ih1 : w_hh1;
        float v[2][4];
#pragma unroll
        for (int j = 0; j < 2; j++) {
            int g = (2 * p + j) * 128 + n;
#pragma unroll
            for (int q = 0; q < 4; q++) {
                int kk = (kp & 7) * 16 + (q >> 1) * 8 + c * 2 + (q & 1);
                v[j][q] = src[g * 128 + kk];
            }
        }
        d_WB1u[idx] = make_uint4(
            pack_bf2(v[0][0], v[0][1]), pack_bf2(v[0][2], v[0][3]),
            pack_bf2(v[1][0], v[1][1]), pack_bf2(v[1][2], v[1][3]));
    }
    if (idx < 512) {
        d_B0[idx] = b_ih0[idx] + b_hh0[idx];
        d_B1[idx] = b_ih1[idx] + b_hh1[idx];
    }
}

__device__ __forceinline__ void mma16(float acc[4], uint32_t a0, uint32_t a1,
                                      uint32_t a2, uint32_t a3, uint32_t b0, uint32_t b1)
{
    asm volatile(
        "mma.sync.aligned.m16n8k16.row.col.f32.bf16.bf16.f32 "
        "{%0,%1,%2,%3}, {%4,%5,%6,%7}, {%8,%9}, {%0,%1,%2,%3};\n"
        : "+f"(acc[0]), "+f"(acc[1]), "+f"(acc[2]), "+f"(acc[3])
        : "r"(a0), "r"(a1), "r"(a2), "r"(a3), "r"(b0), "r"(b1));
}

#define LDSM4(a0, a1, a2, a3, addr)                                       \
    asm volatile("ldmatrix.sync.aligned.m8n8.x4.shared.b16 "              \
                 "{%0,%1,%2,%3}, [%4];"                                   \
                 : "=r"(a0), "=r"(a1), "=r"(a2), "=r"(a3) : "r"(addr))

__device__ __forceinline__ float tanha(float x)
{
    float y;
    asm("tanh.approx.f32 %0, %1;" : "=f"(y) : "f"(x));
    return y;
}
__device__ __forceinline__ float sigf(float x)
{
    return fmaf(tanha(0.5f * x), 0.5f, 0.5f);
}

// 4 gate-type mmas from two packed uint4 weight rows
__device__ __forceinline__ void mma4(float acc[4][4], uint32_t a0, uint32_t a1,
                                     uint32_t a2, uint32_t a3, uint4 w01, uint4 w23)
{
    mma16(acc[0], a0, a1, a2, a3, w01.x, w01.y);
    mma16(acc[1], a0, a1, a2, a3, w01.z, w01.w);
    mma16(acc[2], a0, a1, a2, a3, w23.x, w23.y);
    mma16(acc[3], a0, a1, a2, a3, w23.z, w23.w);
}

__device__ __forceinline__ void acc_init(float acc[4][4], const float* bs)
{
#pragma unroll
    for (int gt = 0; gt < 4; gt++) {
        acc[gt][0] = bs[gt * 2];  acc[gt][1] = bs[gt * 2 + 1];
        acc[gt][2] = bs[gt * 2];  acc[gt][3] = bs[gt * 2 + 1];
    }
}

__device__ __forceinline__ void cell(const float acc[4][4], float* cs,
                                     uint32_t* __restrict__ hdst, int r0, int c0, int w)
{
#pragma unroll
    for (int rg = 0; rg < 2; rg++) {
        float hv[2];
#pragma unroll
        for (int j = 0; j < 2; j++) {
            int idx = rg * 2 + j;
            float i_ = sigf(acc[0][idx]);
            float f_ = sigf(acc[1][idx]);
            float g_ = tanha(acc[2][idx]);
            float o_ = sigf(acc[3][idx]);
            float cv = fmaf(f_, cs[idx], i_ * g_);
            cs[idx] = cv;
            hv[j] = o_ * tanha(cv);
        }
        hdst[(r0 + 8 * rg) * HSTR + w * 4 + c0] = pack_bf2(hv[0], hv[1]);
    }
}

#define SW0_U4 (16 * L0KP * 2 * 32)           // 9216 uint4  = 147456 B
#define SW1_U4 (16 * L1C * 2 * 32)            // 3072 uint4  = 49152 B
#define HBUF   (2 * MROWS * HSTR)             // uint32 per layer ping-pong pair
#define SMEM_SZ (SW0_U4 * 16 + SW1_U4 * 16 + 2 * HBUF * 4)   // 216064 B

__global__ void __launch_bounds__(NTHR, 1)
lstm_main(const float* __restrict__ hr, const float* __restrict__ glu,
          const float* __restrict__ w1, const float* __restrict__ b1,
          const float* __restrict__ w2, const float* __restrict__ b2,
          float* __restrict__ out)
{
    extern __shared__ char smem_raw[];
    uint4*    sw0 = reinterpret_cast<uint4*>(smem_raw);
    uint4*    sw1 = reinterpret_cast<uint4*>(smem_raw + SW0_U4 * 16);
    uint32_t* h0e = reinterpret_cast<uint32_t*>(smem_raw + SW0_U4 * 16 + SW1_U4 * 16);
    uint32_t* h1e = h0e + HBUF;
    float*    hid_s = reinterpret_cast<float*>(smem_raw);   // overlay after loop

    const int tid = threadIdx.x;
    const int l = tid & 31, w = tid >> 5;
    const int r0 = l >> 2, c0 = l & 3;
    const int B0 = blockIdx.x * MROWS;

    // ---- load resident weights ----
    for (int i = tid; i < SW0_U4; i += NTHR) sw0[i] = d_WB0u[i];
    for (int i = tid; i < SW1_U4; i += NTHR) {
        int ll = i & 31, r = i >> 5;
        int p = r & 1, rr = r >> 1;
        int kp = rr % L1C, ww = rr / L1C;
        sw1[i] = d_WB1u[((ww * L1KP + kp) * 2 + p) * 32 + ll];
    }
    for (int i = tid; i < HBUF; i += NTHR) { h0e[i] = 0u; h1e[i] = 0u; }
    __syncthreads();
    if (tid < MROWS)    // x_0 -> pair 64 of h0e phase 0
        h0e[tid * HSTR + 64] = pack_bf2(hr[(B0 + tid) * T_STEPS], glu[(B0 + tid) * T_STEPS]);

    float bs0[8], bs1[8];
#pragma unroll
    for (int gt = 0; gt < 4; gt++)
#pragma unroll
        for (int j = 0; j < 2; j++) {
            int g = gt * 128 + w * 8 + 2 * c0 + j;
            bs0[gt * 2 + j] = d_B0[g];
            bs1[gt * 2 + j] = d_B1[g];
        }

    float cs0[4] = {0.f, 0.f, 0.f, 0.f};
    float cs1[4] = {0.f, 0.f, 0.f, 0.f};

    // per-thread ldmatrix address offset: lanes 0-15 -> rows, 16-31 -> +16B
    const uint32_t aoff = (uint32_t)((l & 15) * (HSTR * 4) + ((l >> 4) << 4));
    const uint32_t h0u = (uint32_t)__cvta_generic_to_shared(h0e) + aoff;
    const uint32_t h1u = (uint32_t)__cvta_generic_to_shared(h1e) + aoff;

    const uint4* ws0 = sw0 + (w * L0KP) * 64 + l;             // [kp*64 + p*32]
    const uint4* ws1 = sw1 + (w * L1C) * 64 + l;
    const uint4* wg1 = d_WB1u + ((w * L1KP + L1C) * 2) * 32 + l;   // streamed s: [s*64 + p*32]

    __syncthreads();

    // ---- prologue: h0_0 from [h0=0, x_0] ----
    {
        float acc0[4][4];
        acc_init(acc0, bs0);
#pragma unroll
        for (int kp = 0; kp < L0KP; kp++) {
            uint32_t a0, a1, a2, a3;
            LDSM4(a0, a1, a2, a3, h0u + kp * 32);
            mma4(acc0, a0, a1, a2, a3, ws0[kp * 64], ws0[kp * 64 + 32]);
        }
        cell(acc0, cs0, h0e + MROWS * HSTR, r0, c0, w);
        if (tid < MROWS)
            h0e[MROWS * HSTR + tid * HSTR + 64] =
                pack_bf2(hr[(B0 + tid) * T_STEPS + 1], glu[(B0 + tid) * T_STEPS + 1]);
        __syncthreads();
    }

    int cur = 1;
#pragma unroll 1
    for (int t = 0; t < T_STEPS; t++) {
        const int nxt = cur ^ 1;
        const uint32_t h0b = h0u + cur * PB;      // h0_t (+ x_{t+1})
        const uint32_t h1b = h1u + cur * PB;      // h1_{t-1}
        float acc1[4][4], acc0[4][4];
        acc_init(acc1, bs1);
        acc_init(acc0, bs0);

        uint4 Wc0 = __ldg(wg1), Wc1 = __ldg(wg1 + 32);

        // ---- merged h0 pass: layer1 (kp<8) + layer0 (all 9 kp) ----
#pragma unroll
        for (int kp = 0; kp < L0KP; kp++) {
            uint32_t a0, a1, a2, a3;
            LDSM4(a0, a1, a2, a3, h0b + kp * 32);
            if (kp < 8) {
                if (kp < L1C) {
                    mma4(acc1, a0, a1, a2, a3, ws1[kp * 64], ws1[kp * 64 + 32]);
                } else {
                    uint4 w01 = Wc0, w23 = Wc1;
                    int s = kp - L1C;                       // 0..4
                    Wc0 = __ldg(wg1 + (s + 1) * 64);
                    Wc1 = __ldg(wg1 + (s + 1) * 64 + 32);
                    mma4(acc1, a0, a1, a2, a3, w01, w23);
                }
            }
            mma4(acc0, a0, a1, a2, a3, ws0[kp * 64], ws0[kp * 64 + 32]);
        }

        // ---- cell0 (MUFU) issues under the h1-part tensor stream ----
        cell(acc0, cs0, h0e + nxt * MROWS * HSTR, r0, c0, w);   // h0_{t+1}
        if (tid < MROWS && t + 2 < T_STEPS)
            h0e[nxt * MROWS * HSTR + tid * HSTR + 64] =
                pack_bf2(hr[(B0 + tid) * T_STEPS + t + 2],
                         glu[(B0 + tid) * T_STEPS + t + 2]);

        // ---- h1 pass: layer1 kp 8..15 (streamed s = 5..12) ----
#pragma unroll
        for (int kp = 0; kp < 8; kp++) {
            uint32_t a0, a1, a2, a3;
            LDSM4(a0, a1, a2, a3, h1b + kp * 32);
            uint4 w01 = Wc0, w23 = Wc1;
            int s = 5 + kp;
            if (s + 1 < NSTREAM) {
                Wc0 = __ldg(wg1 + (s + 1) * 64);
                Wc1 = __ldg(wg1 + (s + 1) * 64 + 32);
            }
            mma4(acc1, a0, a1, a2, a3, w01, w23);
        }

        cell(acc1, cs1, h1e + nxt * MROWS * HSTR, r0, c0, w);   // h1_t

        __syncthreads();
        cur = nxt;
    }
    // final h1_511 in h1e phase cur; smem weights now dead.

    // ---- head: hidden = relu(h1 @ w1^T + b1) ----
    if (tid < 256) {
        int ff = tid & 63;
        int mq = tid >> 6;
        const float2* w1p = reinterpret_cast<const float2*>(w1 + ff * HID);
#pragma unroll
        for (int j = 0; j < 4; j++) {
            int m = mq + j * 4;
            float s = b1[ff];
            const uint32_t* hp = h1e + cur * MROWS * HSTR + m * HSTR;
#pragma unroll 8
            for (int p = 0; p < 64; p++) {
                float2 hv = __bfloat1622float2(
                    *reinterpret_cast<const __nv_bfloat162*>(&hp[p]));
                float2 wv = w1p[p];
                s = fmaf(hv.x, wv.x, s);
                s = fmaf(hv.y, wv.y, s);
            }
            hid_s[m * 64 + ff] = fmaxf(s, 0.f);
        }
    }
    __syncthreads();

    // ---- head: out = hidden @ w2^T + b2 ----
    if (tid < 32) {
        int m = tid >> 1, o = tid & 1;
        float s = b2[o];
#pragma unroll 8
        for (int k = 0; k < 64; k++)
            s = fmaf(hid_s[m * 64 + k], w2[o * 64 + k], s);
        out[(B0 + m) * 2 + o] = s;
    }
}

extern "C" void kernel_launch(void* const* d_in, const int* in_sizes, int n_in,
                              void* d_out, int out_size)
{
    const float* hr   = (const float*)d_in[0];
    const float* glu  = (const float*)d_in[1];
    const float* wih0 = (const float*)d_in[2];
    const float* whh0 = (const float*)d_in[3];
    const float* bih0 = (const float*)d_in[4];
    const float* bhh0 = (const float*)d_in[5];
    const float* wih1 = (const float*)d_in[6];
    const float* whh1 = (const float*)d_in[7];
    const float* bih1 = (const float*)d_in[8];
    const float* bhh1 = (const float*)d_in[9];
    const float* w1   = (const float*)d_in[10];
    const float* b1   = (const float*)d_in[11];
    const float* w2   = (const float*)d_in[12];
    const float* b2   = (const float*)d_in[13];
    float* out = (float*)d_out;

    cudaFuncSetAttribute(lstm_main, cudaFuncAttributeMaxDynamicSharedMemorySize, SMEM_SZ);

    prep_kernel<<<128, 256>>>(whh0, wih0, bih0, bhh0, wih1, whh1, bih1, bhh1);
    lstm_main<<<NCTA, NTHR, SMEM_SZ>>>(hr, glu, w1, b1, w2, b2, out);
}